// round 15
// baseline (speedup 1.0000x reference)
#include <cuda_runtime.h>
#include <math.h>
#include <stdint.h>

#define TT 512
#define CC 128
#define HH 512
#define ROWS 1024   // B*T
#define CHUNK 32    // k-chunk for GEMM staging

// ---------------- scratch ----------------
__device__ float g_hs [ROWS*CC];
__device__ float g_r  [ROWS*CC];
__device__ float g_k  [ROWS*CC];
__device__ float g_v  [ROWS*CC];
__device__ float g_wk [ROWS*CC];
__device__ float g_y  [ROWS*CC];
__device__ float g_h2 [ROWS*CC];
__device__ float g_mid[ROWS*HH];

// ---------------- helpers ----------------
__device__ __forceinline__ float wsum(float x) {
    #pragma unroll
    for (int o = 16; o; o >>= 1) x += __shfl_xor_sync(0xffffffffu, x, o);
    return x;
}
__device__ __forceinline__ float rcpa(float x) {
    float r; asm("rcp.approx.f32 %0, %1;" : "=f"(r) : "f"(x)); return r;
}
typedef unsigned long long ull;
__device__ __forceinline__ ull pack2(float x, float y) {
    ull r; asm("mov.b64 %0, {%1, %2};" : "=l"(r) : "f"(x), "f"(y)); return r;
}
__device__ __forceinline__ void unpack2(ull p, float& x, float& y) {
    asm("mov.b64 {%0, %1}, %2;" : "=f"(x), "=f"(y) : "l"(p));
}
__device__ __forceinline__ ull fma2(ull a, ull b, ull c) {
    ull d; asm("fma.rn.f32x2 %0, %1, %2, %3;" : "=l"(d) : "l"(a), "l"(b), "l"(c)); return d;
}
__device__ __forceinline__ ull mul2(ull a, ull b) {
    ull d; asm("mul.rn.f32x2 %0, %1, %2;" : "=l"(d) : "l"(a), "l"(b)); return d;
}
__device__ __forceinline__ ull add2(ull a, ull b) {
    ull d; asm("add.rn.f32x2 %0, %1, %2;" : "=l"(d) : "l"(a), "l"(b)); return d;
}
__device__ __forceinline__ void cpasync16(uint32_t saddr, const void* g) {
    asm volatile("cp.async.ca.shared.global [%0], [%1], 16;" :: "r"(saddr), "l"(g));
}
__device__ __forceinline__ void cpcommit() { asm volatile("cp.async.commit_group;"); }
template<int N> __device__ __forceinline__ void cpwait() {
    asm volatile("cp.async.wait_group %0;" :: "n"(N));
}

// ---------------- fused LN1 + TemporalShift: 8 rows/block, grid 128 ----------------
__global__ void __launch_bounds__(256)
ln_shift_kernel(const float* __restrict__ x,
                const float* __restrict__ gam, const float* __restrict__ bet,
                const float* __restrict__ mu, float* __restrict__ hs) {
    __shared__ float sh[10][CC];
    const int tid = threadIdx.x;
    const int w = tid >> 5, lane = tid & 31;
    const int b  = blockIdx.x >> 6;
    const int t0 = (blockIdx.x & 63) << 3;

    float4 g4 = *(const float4*)(gam + (lane << 2));
    float4 b4 = *(const float4*)(bet + (lane << 2));

    for (int hr = w; hr < 10; hr += 8) {
        int t = t0 - 1 + hr;
        bool ok = (t >= 0) && (t < TT);
        float4 xv = make_float4(0.f, 0.f, 0.f, 0.f);
        if (ok) xv = *(const float4*)(x + (size_t)((b << 9) + t)*CC + (lane << 2));
        float mean = wsum((xv.x + xv.y) + (xv.z + xv.w)) * (1.0f/CC);
        float d0 = xv.x - mean, d1 = xv.y - mean, d2 = xv.z - mean, d3 = xv.w - mean;
        float rs = rsqrtf(wsum((d0*d0 + d1*d1) + (d2*d2 + d3*d3)) * (1.0f/CC) + 1e-5f);
        int c = lane << 2;
        sh[hr][c+0] = ok ? d0*rs*g4.x + b4.x : 0.f;
        sh[hr][c+1] = ok ? d1*rs*g4.y + b4.y : 0.f;
        sh[hr][c+2] = ok ? d2*rs*g4.z + b4.z : 0.f;
        sh[hr][c+3] = ok ? d3*rs*g4.w + b4.w : 0.f;
    }
    __syncthreads();
    for (int i = tid; i < 8*CC; i += 256) {
        int rl = i >> 7, c = i & (CC-1);
        float val = sh[rl+1][c];
        float shv = (c < CC/2) ? sh[rl][c] : sh[rl+2][c];
        hs[(size_t)((b << 9) + t0 + rl)*CC + c] = val + mu[c]*shv;
    }
}

// ---------------- GEMM v2 core: 8 rows x 128 cols, 256 thr, 8-way split-K ----
// A fully prefetched to registers at entry (NC floats/thread) -> zero exposed
// global latency in the chunk loop. B double-buffered via cp.async.
struct __align__(16) SmemGemm {
    float Bs[2][CHUNK][CC];      // 32 KB (aliased as split-K reduce buffer)
    ull   AsD[2][CHUNK][8];      //  4 KB (pre-duplicated f32x2 A)
};

template<int K>
__device__ __forceinline__ void gemm_v2(const float* __restrict__ A, int lda,
                                        const float* __restrict__ W, int ldw, int bn,
                                        float (&outv)[4]) {
    __shared__ SmemGemm sg;
    const int tid = threadIdx.x, w = tid >> 5, lane = tid & 31;
    const int bm = blockIdx.y << 3;
    constexpr int NC = K / CHUNK;
    uint32_t bs_base = (uint32_t)__cvta_generic_to_shared(&sg.Bs[0][0][0]);

    const int ak = tid >> 3, ar = tid & 7;

    #define STAGE_B(c, buf) do {                                                 \
        const float* _src = W + (size_t)((c)*CHUNK)*ldw + bn;                    \
        _Pragma("unroll")                                                        \
        for (int _j = 0; _j < 4; _j++) {                                         \
            int _idx = tid + _j*256;                                             \
            int _kk = _idx >> 5, _q = _idx & 31;                                 \
            cpasync16(bs_base + (uint32_t)(((buf)*CHUNK + _kk)*CC + (_q<<2))*4u, \
                      _src + (size_t)_kk*ldw + (_q<<2));                         \
        }                                                                        \
        cpcommit();                                                              \
    } while (0)

    STAGE_B(0, 0);

    // prefetch ALL of this thread's A contributions (independent LDGs, MLP=NC)
    float aAll[NC];
    #pragma unroll
    for (int c = 0; c < NC; c++)
        aAll[c] = A[(size_t)(bm + ar)*lda + c*CHUNK + ak];

    sg.AsD[0][ak][ar] = pack2(aAll[0], aAll[0]);

    ull acc[8][2];
    #pragma unroll
    for (int r = 0; r < 8; r++) { acc[r][0] = 0ull; acc[r][1] = 0ull; }

    #pragma unroll 1
    for (int c = 0; c < NC; c++) {
        if (c + 1 < NC) {
            STAGE_B(c+1, (c+1)&1);
            cpwait<1>();
        } else {
            cpwait<0>();
        }
        __syncthreads();
        const int buf = c & 1;
        #pragma unroll
        for (int j = 0; j < CHUNK/8; j++) {
            const int kk = w*(CHUNK/8) + j;
            const ull* ad = &sg.AsD[buf][kk][0];
            ulonglong2 a01 = *(const ulonglong2*)(ad);
            ulonglong2 a23 = *(const ulonglong2*)(ad + 2);
            ulonglong2 a45 = *(const ulonglong2*)(ad + 4);
            ulonglong2 a67 = *(const ulonglong2*)(ad + 6);
            ulonglong2 b   = *(const ulonglong2*)&sg.Bs[buf][kk][lane << 2];
            acc[0][0]=fma2(a01.x,b.x,acc[0][0]); acc[0][1]=fma2(a01.x,b.y,acc[0][1]);
            acc[1][0]=fma2(a01.y,b.x,acc[1][0]); acc[1][1]=fma2(a01.y,b.y,acc[1][1]);
            acc[2][0]=fma2(a23.x,b.x,acc[2][0]); acc[2][1]=fma2(a23.x,b.y,acc[2][1]);
            acc[3][0]=fma2(a23.y,b.x,acc[3][0]); acc[3][1]=fma2(a23.y,b.y,acc[3][1]);
            acc[4][0]=fma2(a45.x,b.x,acc[4][0]); acc[4][1]=fma2(a45.x,b.y,acc[4][1]);
            acc[5][0]=fma2(a45.y,b.x,acc[5][0]); acc[5][1]=fma2(a45.y,b.y,acc[5][1]);
            acc[6][0]=fma2(a67.x,b.x,acc[6][0]); acc[6][1]=fma2(a67.x,b.y,acc[6][1]);
            acc[7][0]=fma2(a67.y,b.x,acc[7][0]); acc[7][1]=fma2(a67.y,b.y,acc[7][1]);
        }
        if (c + 1 < NC) sg.AsD[(c+1)&1][ak][ar] = pack2(aAll[c+1], aAll[c+1]);
        __syncthreads();
    }
    #undef STAGE_B

    // split-K reduce through smem (aliases Bs: exactly 32 KB)
    float* Red = (float*)&sg.Bs[0][0][0];
    #pragma unroll
    for (int r = 0; r < 8; r++) {
        float x0, x1, x2, x3;
        unpack2(acc[r][0], x0, x1);
        unpack2(acc[r][1], x2, x3);
        *(float4*)&Red[((w << 3) + r)*CC + (lane << 2)] = make_float4(x0, x1, x2, x3);
    }
    __syncthreads();
    const int rr = tid >> 5, c4 = (tid & 31) << 2;
    float4 s = *(float4*)&Red[(rr)*CC + c4];
    #pragma unroll
    for (int j = 1; j < 8; j++) {
        float4 t = *(float4*)&Red[((j << 3) + rr)*CC + c4];
        s.x += t.x; s.y += t.y; s.z += t.z; s.w += t.w;
    }
    outv[0] = s.x; outv[1] = s.y; outv[2] = s.z; outv[3] = s.w;
}

// ---------------- fused r/k/v GEMMs (z selects matrix) ----------------
__global__ void __launch_bounds__(256, 1)
rkv_kernel(const float* __restrict__ hs,
           const float* __restrict__ Wr, const float* __restrict__ br,
           const float* __restrict__ Wk, const float* __restrict__ bk,
           const float* __restrict__ Wv, const float* __restrict__ bv,
           float* __restrict__ ro, float* __restrict__ ko, float* __restrict__ vo) {
    const int z = blockIdx.z;
    const float* W  = (z == 0) ? Wr : (z == 1) ? Wk : Wv;
    const float* bb = (z == 0) ? br : (z == 1) ? bk : bv;
    float* o        = (z == 0) ? ro : (z == 1) ? ko : vo;
    float ov[4];
    gemm_v2<CC>(hs, CC, W, CC, 0, ov);
    const int r = threadIdx.x >> 5, lane = threadIdx.x & 31;
    const int m = (blockIdx.y << 3) + r;
    float4 bias4 = *(const float4*)(bb + (lane << 2));
    float v0 = ov[0] + bias4.x, v1 = ov[1] + bias4.y;
    float v2 = ov[2] + bias4.z, v3 = ov[3] + bias4.w;
    if (z == 0) {
        v0 = 1.0f/(1.0f + expf(-v0)); v1 = 1.0f/(1.0f + expf(-v1));
        v2 = 1.0f/(1.0f + expf(-v2)); v3 = 1.0f/(1.0f + expf(-v3));
    }
    *(float4*)(o + (size_t)m*CC + (lane << 2)) = make_float4(v0, v1, v2, v3);
}

// ---------------- WKV: wk = r * x_f (x_b == x_f identity) ----------------
// 1024 thr = 32 warps = 8 rows x 4 segs. Lane = 16h + p: half h = even/odd l,
// p owns 8 channels; z reduced over the 16-lane half via shfl. Grid 128.
__global__ void __launch_bounds__(1024, 1)
wkv_kernel(const float* __restrict__ k, const float* __restrict__ v,
           const float* __restrict__ r, const float* __restrict__ wd,
           float* __restrict__ wk) {
    __shared__ float s_acc[4][8][CC];
    const int tid = threadIdx.x;
    const int wid = tid >> 5, lane = tid & 31;
    const int seg = wid >> 3, rloc = wid & 7;
    const int row = (blockIdx.x << 3) + rloc;
    const int bb  = row >> 9;
    const int h = lane >> 4, p = lane & 15;
    const int c0 = p << 3;

    float bv8[8];
    {
        float4 k0 = *(const float4*)(k  + (size_t)row*CC + c0);
        float4 k1 = *(const float4*)(k  + (size_t)row*CC + c0 + 4);
        float4 w0 = *(const float4*)(wd + c0);
        float4 w1 = *(const float4*)(wd + c0 + 4);
        bv8[0] = k0.x * (-expf(w0.x)); bv8[1] = k0.y * (-expf(w0.y));
        bv8[2] = k0.z * (-expf(w0.z)); bv8[3] = k0.w * (-expf(w0.w));
        bv8[4] = k1.x * (-expf(w1.x)); bv8[5] = k1.y * (-expf(w1.y));
        bv8[6] = k1.z * (-expf(w1.z)); bv8[7] = k1.w * (-expf(w1.w));
    }
    float amax = bv8[0];
    #pragma unroll
    for (int i = 1; i < 8; i++) amax = fmaxf(amax, bv8[i]);
    #pragma unroll
    for (int o = 16; o; o >>= 1) amax = fmaxf(amax, __shfl_xor_sync(0xffffffffu, amax, o));
    #pragma unroll
    for (int i = 0; i < 8; i++) bv8[i] -= amax;

    const float inv511 = 1.0f/511.0f;
    const int l0 = seg << 7;
    const float s0 = (float)(511 - (l0 + h)) * inv511;
    ull E2[4], g2[4];
    #pragma unroll
    for (int j = 0; j < 4; j++) {
        E2[j] = pack2(expf(bv8[2*j]*s0),           expf(bv8[2*j+1]*s0));
        g2[j] = pack2(expf(-2.0f*bv8[2*j]*inv511), expf(-2.0f*bv8[2*j+1]*inv511));
    }
    ull acc2[4] = {0ull, 0ull, 0ull, 0ull};
    const float* vp = v + ((size_t)(bb << 9) + l0 + h)*CC + c0;

    #pragma unroll 4
    for (int i = 0; i < 64; i++) {
        ull t = add2(add2(E2[0], E2[1]), add2(E2[2], E2[3]));
        float zl, zh; unpack2(t, zl, zh);
        float z = zl + zh;
        #pragma unroll
        for (int o = 8; o; o >>= 1) z += __shfl_xor_sync(0xffffffffu, z, o);
        float inv = rcpa(z + 1e-6f);
        ull invd = pack2(inv, inv);
        ulonglong2 v01 = *(const ulonglong2*)(vp);
        ulonglong2 v23 = *(const ulonglong2*)(vp + 4);
        acc2[0] = fma2(mul2(E2[0], invd), v01.x, acc2[0]);
        acc2[1] = fma2(mul2(E2[1], invd), v01.y, acc2[1]);
        acc2[2] = fma2(mul2(E2[2], invd), v23.x, acc2[2]);
        acc2[3] = fma2(mul2(E2[3], invd), v23.y, acc2[3]);
        E2[0] = mul2(E2[0], g2[0]); E2[1] = mul2(E2[1], g2[1]);
        E2[2] = mul2(E2[2], g2[2]); E2[3] = mul2(E2[3], g2[3]);
        vp += 2*CC;
    }

    #pragma unroll
    for (int j = 0; j < 4; j++) {
        float x, y; unpack2(acc2[j], x, y);
        x += __shfl_xor_sync(0xffffffffu, x, 16);
        y += __shfl_xor_sync(0xffffffffu, y, 16);
        if (h == 0) {
            s_acc[seg][rloc][c0 + 2*j    ] = x;
            s_acc[seg][rloc][c0 + 2*j + 1] = y;
        }
    }
    __syncthreads();

    const int rl = tid >> 7, c = tid & (CC-1);
    float sum = (s_acc[0][rl][c] + s_acc[1][rl][c]) + (s_acc[2][rl][c] + s_acc[3][rl][c]);
    const int grow = (blockIdx.x << 3) + rl;
    wk[(size_t)grow*CC + c] = r[(size_t)grow*CC + c] * sum;
}

// ---------------- Wo GEMM + residual + LN2 (fused) ----------------
__global__ void __launch_bounds__(256, 1)
wo_ln_kernel(const float* __restrict__ wkin, const float* __restrict__ Wo,
             const float* __restrict__ bo, const float* __restrict__ x,
             const float* __restrict__ g2, const float* __restrict__ be2,
             float* __restrict__ y, float* __restrict__ h2) {
    float ov[4];
    gemm_v2<CC>(wkin, CC, Wo, CC, 0, ov);
    const int r = threadIdx.x >> 5, lane = threadIdx.x & 31;
    const int m = (blockIdx.y << 3) + r;
    float4 bias4 = *(const float4*)(bo  + (lane << 2));
    float4 g4    = *(const float4*)(g2  + (lane << 2));
    float4 b4    = *(const float4*)(be2 + (lane << 2));
    float4 xv = *(const float4*)(x + (size_t)m*CC + (lane << 2));
    float y0 = ov[0] + bias4.x + xv.x;
    float y1 = ov[1] + bias4.y + xv.y;
    float y2 = ov[2] + bias4.z + xv.z;
    float y3 = ov[3] + bias4.w + xv.w;
    *(float4*)(y + (size_t)m*CC + (lane << 2)) = make_float4(y0, y1, y2, y3);
    float mean = wsum((y0 + y1) + (y2 + y3)) * (1.0f/CC);
    float d0 = y0 - mean, d1 = y1 - mean, d2 = y2 - mean, d3 = y3 - mean;
    float rs = rsqrtf(wsum((d0*d0 + d1*d1) + (d2*d2 + d3*d3)) * (1.0f/CC) + 1e-5f);
    *(float4*)(h2 + (size_t)m*CC + (lane << 2)) =
        make_float4(d0*rs*g4.x + b4.x, d1*rs*g4.y + b4.y,
                    d2*rs*g4.z + b4.z, d3*rs*g4.w + b4.w);
}

// ---------------- W1 GEMM + exact gelu ----------------
__global__ void __launch_bounds__(256, 1)
w1_kernel(const float* __restrict__ h2, const float* __restrict__ W1,
          const float* __restrict__ b1, float* __restrict__ mid) {
    const int bn = blockIdx.x << 7;
    float ov[4];
    gemm_v2<CC>(h2, CC, W1, HH, bn, ov);
    const int r = threadIdx.x >> 5, lane = threadIdx.x & 31;
    const int m = (blockIdx.y << 3) + r;
    float4 bias4 = *(const float4*)(b1 + bn + (lane << 2));
    float v0 = ov[0] + bias4.x, v1 = ov[1] + bias4.y;
    float v2 = ov[2] + bias4.z, v3 = ov[3] + bias4.w;
    const float s = 0.70710678118654752f;
    v0 = 0.5f*v0*(1.0f + erff(v0*s));
    v1 = 0.5f*v1*(1.0f + erff(v1*s));
    v2 = 0.5f*v2*(1.0f + erff(v2*s));
    v3 = 0.5f*v3*(1.0f + erff(v3*s));
    *(float4*)(mid + (size_t)m*HH + bn + (lane << 2)) = make_float4(v0, v1, v2, v3);
}

// ---------------- W2 GEMM + residual -> out ----------------
__global__ void __launch_bounds__(256, 1)
w2_kernel(const float* __restrict__ mid, const float* __restrict__ W2,
          const float* __restrict__ b2, const float* __restrict__ y,
          float* __restrict__ out) {
    float ov[4];
    gemm_v2<HH>(mid, HH, W2, CC, 0, ov);
    const int r = threadIdx.x >> 5, lane = threadIdx.x & 31;
    const int m = (blockIdx.y << 3) + r;
    float4 bias4 = *(const float4*)(b2 + (lane << 2));
    float4 yv = *(const float4*)(y + (size_t)m*CC + (lane << 2));
    *(float4*)(out + (size_t)m*CC + (lane << 2)) =
        make_float4(ov[0] + bias4.x + yv.x, ov[1] + bias4.y + yv.y,
                    ov[2] + bias4.z + yv.z, ov[3] + bias4.w + yv.w);
}

// ---------------- launch ----------------
extern "C" void kernel_launch(void* const* d_in, const int* in_sizes, int n_in,
                              void* d_out, int out_size) {
    const float* x       = (const float*)d_in[0];
    const float* ln1_g   = (const float*)d_in[1];
    const float* ln1_b   = (const float*)d_in[2];
    const float* mu      = (const float*)d_in[3];
    const float* Wr      = (const float*)d_in[4];
    const float* br      = (const float*)d_in[5];
    const float* Wk      = (const float*)d_in[6];
    const float* bk      = (const float*)d_in[7];
    const float* Wv      = (const float*)d_in[8];
    const float* bv      = (const float*)d_in[9];
    const float* w_decay = (const float*)d_in[10];
    const float* Wo      = (const float*)d_in[11];
    const float* bo      = (const float*)d_in[12];
    const float* ln2_g   = (const float*)d_in[13];
    const float* ln2_b   = (const float*)d_in[14];
    const float* W1      = (const float*)d_in[15];
    const float* b1      = (const float*)d_in[16];
    const float* W2      = (const float*)d_in[17];
    const float* b2      = (const float*)d_in[18];
    float* out = (float*)d_out;

    float *hs, *r_, *k_, *v_, *wkp, *y, *h2, *mid;
    cudaGetSymbolAddress((void**)&hs,  g_hs);
    cudaGetSymbolAddress((void**)&r_,  g_r);
    cudaGetSymbolAddress((void**)&k_,  g_k);
    cudaGetSymbolAddress((void**)&v_,  g_v);
    cudaGetSymbolAddress((void**)&wkp, g_wk);
    cudaGetSymbolAddress((void**)&y,   g_y);
    cudaGetSymbolAddress((void**)&h2,  g_h2);
    cudaGetSymbolAddress((void**)&mid, g_mid);

    ln_shift_kernel<<<128, 256>>>(x, ln1_g, ln1_b, mu, hs);
    rkv_kernel<<<dim3(1, 128, 3), 256>>>(hs, Wr, br, Wk, bk, Wv, bv, r_, k_, v_);
    wkv_kernel<<<128, 1024>>>(k_, v_, r_, w_decay, wkp);
    wo_ln_kernel<<<dim3(1, 128), 256>>>(wkp, Wo, bo, x, ln2_g, ln2_b, y, h2);
    w1_kernel<<<dim3(4, 128), 256>>>(h2, W1, b1, mid);
    w2_kernel<<<dim3(1, 128), 256>>>(mid, W2, b2, y, out);
}

// round 16
// speedup vs baseline: 1.6316x; 1.6316x over previous
#include <cuda_runtime.h>
#include <math.h>
#include <stdint.h>

#define TT 512
#define CC 128
#define HH 512
#define ROWS 1024   // B*T
#define CHUNK 32    // k-chunk for GEMM staging

// ---------------- scratch ----------------
__device__ float g_hs [ROWS*CC];
__device__ float g_r  [ROWS*CC];
__device__ float g_k  [ROWS*CC];
__device__ float g_v  [ROWS*CC];
__device__ float g_wk [ROWS*CC];
__device__ float g_y  [ROWS*CC];
__device__ float g_h2 [ROWS*CC];
__device__ float g_mid[ROWS*HH];

// ---------------- helpers ----------------
__device__ __forceinline__ float wsum(float x) {
    #pragma unroll
    for (int o = 16; o; o >>= 1) x += __shfl_xor_sync(0xffffffffu, x, o);
    return x;
}
__device__ __forceinline__ float rcpa(float x) {
    float r; asm("rcp.approx.f32 %0, %1;" : "=f"(r) : "f"(x)); return r;
}
typedef unsigned long long ull;
__device__ __forceinline__ ull pack2(float x, float y) {
    ull r; asm("mov.b64 %0, {%1, %2};" : "=l"(r) : "f"(x), "f"(y)); return r;
}
__device__ __forceinline__ void unpack2(ull p, float& x, float& y) {
    asm("mov.b64 {%0, %1}, %2;" : "=f"(x), "=f"(y) : "l"(p));
}
__device__ __forceinline__ ull fma2(ull a, ull b, ull c) {
    ull d; asm("fma.rn.f32x2 %0, %1, %2, %3;" : "=l"(d) : "l"(a), "l"(b), "l"(c)); return d;
}
__device__ __forceinline__ ull mul2(ull a, ull b) {
    ull d; asm("mul.rn.f32x2 %0, %1, %2;" : "=l"(d) : "l"(a), "l"(b)); return d;
}
__device__ __forceinline__ ull add2(ull a, ull b) {
    ull d; asm("add.rn.f32x2 %0, %1, %2;" : "=l"(d) : "l"(a), "l"(b)); return d;
}
__device__ __forceinline__ void cpasync16(uint32_t saddr, const void* g) {
    asm volatile("cp.async.ca.shared.global [%0], [%1], 16;" :: "r"(saddr), "l"(g));
}
__device__ __forceinline__ void cpcommit() { asm volatile("cp.async.commit_group;"); }
template<int N> __device__ __forceinline__ void cpwait() {
    asm volatile("cp.async.wait_group %0;" :: "n"(N));
}

// ---------------- fused LN1 + TemporalShift: 8 rows/block, grid 128 ----------------
__global__ void __launch_bounds__(256)
ln_shift_kernel(const float* __restrict__ x,
                const float* __restrict__ gam, const float* __restrict__ bet,
                const float* __restrict__ mu, float* __restrict__ hs) {
    __shared__ float sh[10][CC];
    const int tid = threadIdx.x;
    const int w = tid >> 5, lane = tid & 31;
    const int b  = blockIdx.x >> 6;
    const int t0 = (blockIdx.x & 63) << 3;

    float4 g4 = *(const float4*)(gam + (lane << 2));
    float4 b4 = *(const float4*)(bet + (lane << 2));

    for (int hr = w; hr < 10; hr += 8) {
        int t = t0 - 1 + hr;
        bool ok = (t >= 0) && (t < TT);
        float4 xv = make_float4(0.f, 0.f, 0.f, 0.f);
        if (ok) xv = *(const float4*)(x + (size_t)((b << 9) + t)*CC + (lane << 2));
        float mean = wsum((xv.x + xv.y) + (xv.z + xv.w)) * (1.0f/CC);
        float d0 = xv.x - mean, d1 = xv.y - mean, d2 = xv.z - mean, d3 = xv.w - mean;
        float rs = rsqrtf(wsum((d0*d0 + d1*d1) + (d2*d2 + d3*d3)) * (1.0f/CC) + 1e-5f);
        int c = lane << 2;
        sh[hr][c+0] = ok ? d0*rs*g4.x + b4.x : 0.f;
        sh[hr][c+1] = ok ? d1*rs*g4.y + b4.y : 0.f;
        sh[hr][c+2] = ok ? d2*rs*g4.z + b4.z : 0.f;
        sh[hr][c+3] = ok ? d3*rs*g4.w + b4.w : 0.f;
    }
    __syncthreads();
    for (int i = tid; i < 8*CC; i += 256) {
        int rl = i >> 7, c = i & (CC-1);
        float val = sh[rl+1][c];
        float shv = (c < CC/2) ? sh[rl][c] : sh[rl+2][c];
        hs[(size_t)((b << 9) + t0 + rl)*CC + c] = val + mu[c]*shv;
    }
}

// ---------------- GEMM v2 core (round-5 proven): 8x128, 256 thr, 8-way split-K ----
struct __align__(16) SmemGemm {
    float Bs[2][CHUNK][CC];      // 32 KB (aliased as split-K reduce buffer)
    ull   AsD[2][CHUNK][8];      //  4 KB (pre-duplicated f32x2 A)
};

template<int K>
__device__ __forceinline__ void gemm_v2(const float* __restrict__ A, int lda,
                                        const float* __restrict__ W, int ldw, int bn,
                                        float (&outv)[4]) {
    __shared__ SmemGemm sg;
    const int tid = threadIdx.x, w = tid >> 5, lane = tid & 31;
    const int bm = blockIdx.y << 3;
    constexpr int NC = K / CHUNK;
    uint32_t bs_base = (uint32_t)__cvta_generic_to_shared(&sg.Bs[0][0][0]);

    const int ak = tid >> 3, ar = tid & 7;

    #define STAGE_B(c, buf) do {                                                 \
        const float* _src = W + (size_t)((c)*CHUNK)*ldw + bn;                    \
        _Pragma("unroll")                                                        \
        for (int _j = 0; _j < 4; _j++) {                                         \
            int _idx = tid + _j*256;                                             \
            int _kk = _idx >> 5, _q = _idx & 31;                                 \
            cpasync16(bs_base + (uint32_t)(((buf)*CHUNK + _kk)*CC + (_q<<2))*4u, \
                      _src + (size_t)_kk*ldw + (_q<<2));                         \
        }                                                                        \
        cpcommit();                                                              \
    } while (0)

    STAGE_B(0, 0);
    float aCur = A[(size_t)(bm + ar)*lda + ak];
    sg.AsD[0][ak][ar] = pack2(aCur, aCur);

    ull acc[8][2];
    #pragma unroll
    for (int r = 0; r < 8; r++) { acc[r][0] = 0ull; acc[r][1] = 0ull; }

    #pragma unroll 1
    for (int c = 0; c < NC; c++) {
        float aNext = 0.f;
        if (c + 1 < NC) {
            STAGE_B(c+1, (c+1)&1);
            aNext = A[(size_t)(bm + ar)*lda + (c+1)*CHUNK + ak];
            cpwait<1>();
        } else {
            cpwait<0>();
        }
        __syncthreads();
        const int buf = c & 1;
        #pragma unroll
        for (int j = 0; j < CHUNK/8; j++) {
            const int kk = w*(CHUNK/8) + j;
            const ull* ad = &sg.AsD[buf][kk][0];
            ulonglong2 a01 = *(const ulonglong2*)(ad);
            ulonglong2 a23 = *(const ulonglong2*)(ad + 2);
            ulonglong2 a45 = *(const ulonglong2*)(ad + 4);
            ulonglong2 a67 = *(const ulonglong2*)(ad + 6);
            ulonglong2 b   = *(const ulonglong2*)&sg.Bs[buf][kk][lane << 2];
            acc[0][0]=fma2(a01.x,b.x,acc[0][0]); acc[0][1]=fma2(a01.x,b.y,acc[0][1]);
            acc[1][0]=fma2(a01.y,b.x,acc[1][0]); acc[1][1]=fma2(a01.y,b.y,acc[1][1]);
            acc[2][0]=fma2(a23.x,b.x,acc[2][0]); acc[2][1]=fma2(a23.x,b.y,acc[2][1]);
            acc[3][0]=fma2(a23.y,b.x,acc[3][0]); acc[3][1]=fma2(a23.y,b.y,acc[3][1]);
            acc[4][0]=fma2(a45.x,b.x,acc[4][0]); acc[4][1]=fma2(a45.x,b.y,acc[4][1]);
            acc[5][0]=fma2(a45.y,b.x,acc[5][0]); acc[5][1]=fma2(a45.y,b.y,acc[5][1]);
            acc[6][0]=fma2(a67.x,b.x,acc[6][0]); acc[6][1]=fma2(a67.x,b.y,acc[6][1]);
            acc[7][0]=fma2(a67.y,b.x,acc[7][0]); acc[7][1]=fma2(a67.y,b.y,acc[7][1]);
        }
        if (c + 1 < NC) sg.AsD[(c+1)&1][ak][ar] = pack2(aNext, aNext);
        __syncthreads();
    }
    #undef STAGE_B

    float* Red = (float*)&sg.Bs[0][0][0];
    #pragma unroll
    for (int r = 0; r < 8; r++) {
        float x0, x1, x2, x3;
        unpack2(acc[r][0], x0, x1);
        unpack2(acc[r][1], x2, x3);
        *(float4*)&Red[((w << 3) + r)*CC + (lane << 2)] = make_float4(x0, x1, x2, x3);
    }
    __syncthreads();
    const int rr = tid >> 5, c4 = (tid & 31) << 2;
    float4 s = *(float4*)&Red[(rr)*CC + c4];
    #pragma unroll
    for (int j = 1; j < 8; j++) {
        float4 t = *(float4*)&Red[((j << 3) + rr)*CC + c4];
        s.x += t.x; s.y += t.y; s.z += t.z; s.w += t.w;
    }
    outv[0] = s.x; outv[1] = s.y; outv[2] = s.z; outv[3] = s.w;
}

// ---------------- fused r/k/v GEMMs (z selects matrix) ----------------
__global__ void __launch_bounds__(256, 1)
rkv_kernel(const float* __restrict__ hs,
           const float* __restrict__ Wr, const float* __restrict__ br,
           const float* __restrict__ Wk, const float* __restrict__ bk,
           const float* __restrict__ Wv, const float* __restrict__ bv,
           float* __restrict__ ro, float* __restrict__ ko, float* __restrict__ vo) {
    const int z = blockIdx.z;
    const float* W  = (z == 0) ? Wr : (z == 1) ? Wk : Wv;
    const float* bb = (z == 0) ? br : (z == 1) ? bk : bv;
    float* o        = (z == 0) ? ro : (z == 1) ? ko : vo;
    float ov[4];
    gemm_v2<CC>(hs, CC, W, CC, 0, ov);
    const int r = threadIdx.x >> 5, lane = threadIdx.x & 31;
    const int m = (blockIdx.y << 3) + r;
    float4 bias4 = *(const float4*)(bb + (lane << 2));
    float v0 = ov[0] + bias4.x, v1 = ov[1] + bias4.y;
    float v2 = ov[2] + bias4.z, v3 = ov[3] + bias4.w;
    if (z == 0) {
        v0 = 1.0f/(1.0f + expf(-v0)); v1 = 1.0f/(1.0f + expf(-v1));
        v2 = 1.0f/(1.0f + expf(-v2)); v3 = 1.0f/(1.0f + expf(-v3));
    }
    *(float4*)(o + (size_t)m*CC + (lane << 2)) = make_float4(v0, v1, v2, v3);
}

// ---------------- WKV v3: 2 rows/warp -> halved v wavefronts ----------------
// Block = 512 thr = 16 warps = 4 row-pairs x 4 segs (128 l each). Grid 128.
// Lane = 16h + p: half h = even/odd l, p owns 8 channels. Each v load feeds
// BOTH rows of the pair (2 independent E-chains per warp, interleaved).
__global__ void __launch_bounds__(512, 1)
wkv_kernel(const float* __restrict__ k, const float* __restrict__ v,
           const float* __restrict__ r, const float* __restrict__ wd,
           float* __restrict__ wk) {
    __shared__ float s_acc[4][8][CC];
    const int tid = threadIdx.x;
    const int wid = tid >> 5, lane = tid & 31;
    const int seg = wid & 3, rp = wid >> 2;          // seg 0..3, row-pair 0..3
    const int row0 = (blockIdx.x << 3) + (rp << 1);
    const int bb  = row0 >> 9;
    const int h = lane >> 4, p = lane & 15;
    const int c0 = p << 3;

    const float inv511 = 1.0f/511.0f;
    const int l0 = seg << 7;
    const float s0 = (float)(511 - (l0 + h)) * inv511;

    float nw[8];
    {
        float4 w0 = *(const float4*)(wd + c0);
        float4 w1 = *(const float4*)(wd + c0 + 4);
        nw[0] = -expf(w0.x); nw[1] = -expf(w0.y); nw[2] = -expf(w0.z); nw[3] = -expf(w0.w);
        nw[4] = -expf(w1.x); nw[5] = -expf(w1.y); nw[6] = -expf(w1.z); nw[7] = -expf(w1.w);
    }

    ull E[2][4], G[2][4], acc[2][4];
    #pragma unroll
    for (int rr = 0; rr < 2; rr++) {
        float bv8[8];
        float4 k0 = *(const float4*)(k + (size_t)(row0 + rr)*CC + c0);
        float4 k1 = *(const float4*)(k + (size_t)(row0 + rr)*CC + c0 + 4);
        bv8[0] = k0.x*nw[0]; bv8[1] = k0.y*nw[1]; bv8[2] = k0.z*nw[2]; bv8[3] = k0.w*nw[3];
        bv8[4] = k1.x*nw[4]; bv8[5] = k1.y*nw[5]; bv8[6] = k1.z*nw[6]; bv8[7] = k1.w*nw[7];
        float amax = bv8[0];
        #pragma unroll
        for (int i = 1; i < 8; i++) amax = fmaxf(amax, bv8[i]);
        #pragma unroll
        for (int o = 16; o; o >>= 1) amax = fmaxf(amax, __shfl_xor_sync(0xffffffffu, amax, o));
        #pragma unroll
        for (int i = 0; i < 8; i++) bv8[i] -= amax;
        #pragma unroll
        for (int j = 0; j < 4; j++) {
            E[rr][j]   = pack2(expf(bv8[2*j]*s0),           expf(bv8[2*j+1]*s0));
            G[rr][j]   = pack2(expf(-2.0f*bv8[2*j]*inv511), expf(-2.0f*bv8[2*j+1]*inv511));
            acc[rr][j] = 0ull;
        }
    }

    const float* vp = v + ((size_t)(bb << 9) + l0 + h)*CC + c0;

    #pragma unroll 2
    for (int i = 0; i < 64; i++) {
        ulonglong2 v01 = *(const ulonglong2*)(vp);
        ulonglong2 v23 = *(const ulonglong2*)(vp + 4);
        #pragma unroll
        for (int rr = 0; rr < 2; rr++) {
            ull t = add2(add2(E[rr][0], E[rr][1]), add2(E[rr][2], E[rr][3]));
            float zl, zh; unpack2(t, zl, zh);
            float z = zl + zh;
            #pragma unroll
            for (int o = 8; o; o >>= 1) z += __shfl_xor_sync(0xffffffffu, z, o);
            float inv = rcpa(z + 1e-6f);
            ull invd = pack2(inv, inv);
            acc[rr][0] = fma2(mul2(E[rr][0], invd), v01.x, acc[rr][0]);
            acc[rr][1] = fma2(mul2(E[rr][1], invd), v01.y, acc[rr][1]);
            acc[rr][2] = fma2(mul2(E[rr][2], invd), v23.x, acc[rr][2]);
            acc[rr][3] = fma2(mul2(E[rr][3], invd), v23.y, acc[rr][3]);
            E[rr][0] = mul2(E[rr][0], G[rr][0]); E[rr][1] = mul2(E[rr][1], G[rr][1]);
            E[rr][2] = mul2(E[rr][2], G[rr][2]); E[rr][3] = mul2(E[rr][3], G[rr][3]);
        }
        vp += 2*CC;
    }

    #pragma unroll
    for (int rr = 0; rr < 2; rr++) {
        #pragma unroll
        for (int j = 0; j < 4; j++) {
            float x, y; unpack2(acc[rr][j], x, y);
            x += __shfl_xor_sync(0xffffffffu, x, 16);
            y += __shfl_xor_sync(0xffffffffu, y, 16);
            if (h == 0) {
                s_acc[seg][(rp << 1) + rr][c0 + 2*j    ] = x;
                s_acc[seg][(rp << 1) + rr][c0 + 2*j + 1] = y;
            }
        }
    }
    __syncthreads();

    for (int idx = tid; idx < 8*CC; idx += 512) {
        const int rl = idx >> 7, c = idx & (CC-1);
        float sum = (s_acc[0][rl][c] + s_acc[1][rl][c]) + (s_acc[2][rl][c] + s_acc[3][rl][c]);
        const int grow = (blockIdx.x << 3) + rl;
        wk[(size_t)grow*CC + c] = r[(size_t)grow*CC + c] * sum;
    }
}

// ---------------- Wo GEMM + residual + LN2 (fused) ----------------
__global__ void __launch_bounds__(256, 1)
wo_ln_kernel(const float* __restrict__ wkin, const float* __restrict__ Wo,
             const float* __restrict__ bo, const float* __restrict__ x,
             const float* __restrict__ g2, const float* __restrict__ be2,
             float* __restrict__ y, float* __restrict__ h2) {
    float ov[4];
    gemm_v2<CC>(wkin, CC, Wo, CC, 0, ov);
    const int r = threadIdx.x >> 5, lane = threadIdx.x & 31;
    const int m = (blockIdx.y << 3) + r;
    float4 bias4 = *(const float4*)(bo  + (lane << 2));
    float4 g4    = *(const float4*)(g2  + (lane << 2));
    float4 b4    = *(const float4*)(be2 + (lane << 2));
    float4 xv = *(const float4*)(x + (size_t)m*CC + (lane << 2));
    float y0 = ov[0] + bias4.x + xv.x;
    float y1 = ov[1] + bias4.y + xv.y;
    float y2 = ov[2] + bias4.z + xv.z;
    float y3 = ov[3] + bias4.w + xv.w;
    *(float4*)(y + (size_t)m*CC + (lane << 2)) = make_float4(y0, y1, y2, y3);
    float mean = wsum((y0 + y1) + (y2 + y3)) * (1.0f/CC);
    float d0 = y0 - mean, d1 = y1 - mean, d2 = y2 - mean, d3 = y3 - mean;
    float rs = rsqrtf(wsum((d0*d0 + d1*d1) + (d2*d2 + d3*d3)) * (1.0f/CC) + 1e-5f);
    *(float4*)(h2 + (size_t)m*CC + (lane << 2)) =
        make_float4(d0*rs*g4.x + b4.x, d1*rs*g4.y + b4.y,
                    d2*rs*g4.z + b4.z, d3*rs*g4.w + b4.w);
}

// ---------------- W1 GEMM + exact gelu ----------------
__global__ void __launch_bounds__(256, 1)
w1_kernel(const float* __restrict__ h2, const float* __restrict__ W1,
          const float* __restrict__ b1, float* __restrict__ mid) {
    const int bn = blockIdx.x << 7;
    float ov[4];
    gemm_v2<CC>(h2, CC, W1, HH, bn, ov);
    const int r = threadIdx.x >> 5, lane = threadIdx.x & 31;
    const int m = (blockIdx.y << 3) + r;
    float4 bias4 = *(const float4*)(b1 + bn + (lane << 2));
    float v0 = ov[0] + bias4.x, v1 = ov[1] + bias4.y;
    float v2 = ov[2] + bias4.z, v3 = ov[3] + bias4.w;
    const float s = 0.70710678118654752f;
    v0 = 0.5f*v0*(1.0f + erff(v0*s));
    v1 = 0.5f*v1*(1.0f + erff(v1*s));
    v2 = 0.5f*v2*(1.0f + erff(v2*s));
    v3 = 0.5f*v3*(1.0f + erff(v3*s));
    *(float4*)(mid + (size_t)m*HH + bn + (lane << 2)) = make_float4(v0, v1, v2, v3);
}

// ---------------- W2 GEMM + residual -> out ----------------
__global__ void __launch_bounds__(256, 1)
w2_kernel(const float* __restrict__ mid, const float* __restrict__ W2,
          const float* __restrict__ b2, const float* __restrict__ y,
          float* __restrict__ out) {
    float ov[4];
    gemm_v2<HH>(mid, HH, W2, CC, 0, ov);
    const int r = threadIdx.x >> 5, lane = threadIdx.x & 31;
    const int m = (blockIdx.y << 3) + r;
    float4 bias4 = *(const float4*)(b2 + (lane << 2));
    float4 yv = *(const float4*)(y + (size_t)m*CC + (lane << 2));
    *(float4*)(out + (size_t)m*CC + (lane << 2)) =
        make_float4(ov[0] + bias4.x + yv.x, ov[1] + bias4.y + yv.y,
                    ov[2] + bias4.z + yv.z, ov[3] + bias4.w + yv.w);
}

// ---------------- launch ----------------
extern "C" void kernel_launch(void* const* d_in, const int* in_sizes, int n_in,
                              void* d_out, int out_size) {
    const float* x       = (const float*)d_in[0];
    const float* ln1_g   = (const float*)d_in[1];
    const float* ln1_b   = (const float*)d_in[2];
    const float* mu      = (const float*)d_in[3];
    const float* Wr      = (const float*)d_in[4];
    const float* br      = (const float*)d_in[5];
    const float* Wk      = (const float*)d_in[6];
    const float* bk      = (const float*)d_in[7];
    const float* Wv      = (const float*)d_in[8];
    const float* bv      = (const float*)d_in[9];
    const float* w_decay = (const float*)d_in[10];
    const float* Wo      = (const float*)d_in[11];
    const float* bo      = (const float*)d_in[12];
    const float* ln2_g   = (const float*)d_in[13];
    const float* ln2_b   = (const float*)d_in[14];
    const float* W1      = (const float*)d_in[15];
    const float* b1      = (const float*)d_in[16];
    const float* W2      = (const float*)d_in[17];
    const float* b2      = (const float*)d_in[18];
    float* out = (float*)d_out;

    float *hs, *r_, *k_, *v_, *wkp, *y, *h2, *mid;
    cudaGetSymbolAddress((void**)&hs,  g_hs);
    cudaGetSymbolAddress((void**)&r_,  g_r);
    cudaGetSymbolAddress((void**)&k_,  g_k);
    cudaGetSymbolAddress((void**)&v_,  g_v);
    cudaGetSymbolAddress((void**)&wkp, g_wk);
    cudaGetSymbolAddress((void**)&y,   g_y);
    cudaGetSymbolAddress((void**)&h2,  g_h2);
    cudaGetSymbolAddress((void**)&mid, g_mid);

    ln_shift_kernel<<<128, 256>>>(x, ln1_g, ln1_b, mu, hs);
    rkv_kernel<<<dim3(1, 128, 3), 256>>>(hs, Wr, br, Wk, bk, Wv, bv, r_, k_, v_);
    wkv_kernel<<<128, 512>>>(k_, v_, r_, w_decay, wkp);
    wo_ln_kernel<<<dim3(1, 128), 256>>>(wkp, Wo, bo, x, ln2_g, ln2_b, y, h2);
    w1_kernel<<<dim3(4, 128), 256>>>(h2, W1, b1, mid);
    w2_kernel<<<dim3(1, 128), 256>>>(mid, W2, b2, y, out);
}

// round 17
// speedup vs baseline: 1.8006x; 1.1036x over previous
#include <cuda_runtime.h>
#include <math.h>
#include <stdint.h>

#define TT 512
#define CC 128
#define HH 512
#define ROWS 1024   // B*T
#define CHUNK 32    // k-chunk for GEMM staging

// ---------------- scratch ----------------
__device__ float g_r  [ROWS*CC];
__device__ float g_k  [ROWS*CC];
__device__ float g_v  [ROWS*CC];
__device__ float g_wk [ROWS*CC];

// ---------------- helpers ----------------
__device__ __forceinline__ float wsum(float x) {
    #pragma unroll
    for (int o = 16; o; o >>= 1) x += __shfl_xor_sync(0xffffffffu, x, o);
    return x;
}
__device__ __forceinline__ float rcpa(float x) {
    float r; asm("rcp.approx.f32 %0, %1;" : "=f"(r) : "f"(x)); return r;
}
typedef unsigned long long ull;
__device__ __forceinline__ ull pack2(float x, float y) {
    ull r; asm("mov.b64 %0, {%1, %2};" : "=l"(r) : "f"(x), "f"(y)); return r;
}
__device__ __forceinline__ void unpack2(ull p, float& x, float& y) {
    asm("mov.b64 {%0, %1}, %2;" : "=f"(x), "=f"(y) : "l"(p));
}
__device__ __forceinline__ ull fma2(ull a, ull b, ull c) {
    ull d; asm("fma.rn.f32x2 %0, %1, %2, %3;" : "=l"(d) : "l"(a), "l"(b), "l"(c)); return d;
}
__device__ __forceinline__ ull mul2(ull a, ull b) {
    ull d; asm("mul.rn.f32x2 %0, %1, %2;" : "=l"(d) : "l"(a), "l"(b)); return d;
}
__device__ __forceinline__ ull add2(ull a, ull b) {
    ull d; asm("add.rn.f32x2 %0, %1, %2;" : "=l"(d) : "l"(a), "l"(b)); return d;
}
__device__ __forceinline__ void cpasync16(uint32_t saddr, const void* g) {
    asm volatile("cp.async.ca.shared.global [%0], [%1], 16;" :: "r"(saddr), "l"(g));
}
__device__ __forceinline__ void cpcommit() { asm volatile("cp.async.commit_group;"); }
template<int N> __device__ __forceinline__ void cpwait() {
    asm volatile("cp.async.wait_group %0;" :: "n"(N));
}

// ---------------- GEMM core (round-5 proven + entry sync, explicit smem) ----------------
// 8 rows x 128 cols, 256 thr, 8-way split-K. A may live in GLOBAL or SHARED
// (generic pointer); B double-buffered via cp.async. Entry __syncthreads()
// protects sg + A-source from the caller's previous stage.
struct __align__(16) SmemGemm {
    float Bs[2][CHUNK][CC];      // 32 KB (aliased as split-K reduce buffer)
    ull   AsD[2][CHUNK][8];      //  4 KB (pre-duplicated f32x2 A)
};

template<int K>
__device__ __forceinline__ void gemm_v2(SmemGemm& sg,
                                        const float* __restrict__ A, int lda, int bm,
                                        const float* __restrict__ W, int ldw, int bn,
                                        float (&outv)[4]) {
    const int tid = threadIdx.x, w = tid >> 5, lane = tid & 31;
    constexpr int NC = K / CHUNK;
    uint32_t bs_base = (uint32_t)__cvta_generic_to_shared(&sg.Bs[0][0][0]);
    const int ak = tid >> 3, ar = tid & 7;

    __syncthreads();    // prior stage done with sg / A-source

    #define STAGE_B(c, buf) do {                                                 \
        const float* _src = W + (size_t)((c)*CHUNK)*ldw + bn;                    \
        _Pragma("unroll")                                                        \
        for (int _j = 0; _j < 4; _j++) {                                         \
            int _idx = tid + _j*256;                                             \
            int _kk = _idx >> 5, _q = _idx & 31;                                 \
            cpasync16(bs_base + (uint32_t)(((buf)*CHUNK + _kk)*CC + (_q<<2))*4u, \
                      _src + (size_t)_kk*ldw + (_q<<2));                         \
        }                                                                        \
        cpcommit();                                                              \
    } while (0)

    STAGE_B(0, 0);
    float aCur = A[(size_t)(bm + ar)*lda + ak];
    sg.AsD[0][ak][ar] = pack2(aCur, aCur);

    ull acc[8][2];
    #pragma unroll
    for (int r = 0; r < 8; r++) { acc[r][0] = 0ull; acc[r][1] = 0ull; }

    #pragma unroll 1
    for (int c = 0; c < NC; c++) {
        float aNext = 0.f;
        if (c + 1 < NC) {
            STAGE_B(c+1, (c+1)&1);
            aNext = A[(size_t)(bm + ar)*lda + (c+1)*CHUNK + ak];
            cpwait<1>();
        } else {
            cpwait<0>();
        }
        __syncthreads();
        const int buf = c & 1;
        #pragma unroll
        for (int j = 0; j < CHUNK/8; j++) {
            const int kk = w*(CHUNK/8) + j;
            const ull* ad = &sg.AsD[buf][kk][0];
            ulonglong2 a01 = *(const ulonglong2*)(ad);
            ulonglong2 a23 = *(const ulonglong2*)(ad + 2);
            ulonglong2 a45 = *(const ulonglong2*)(ad + 4);
            ulonglong2 a67 = *(const ulonglong2*)(ad + 6);
            ulonglong2 b   = *(const ulonglong2*)&sg.Bs[buf][kk][lane << 2];
            acc[0][0]=fma2(a01.x,b.x,acc[0][0]); acc[0][1]=fma2(a01.x,b.y,acc[0][1]);
            acc[1][0]=fma2(a01.y,b.x,acc[1][0]); acc[1][1]=fma2(a01.y,b.y,acc[1][1]);
            acc[2][0]=fma2(a23.x,b.x,acc[2][0]); acc[2][1]=fma2(a23.x,b.y,acc[2][1]);
            acc[3][0]=fma2(a23.y,b.x,acc[3][0]); acc[3][1]=fma2(a23.y,b.y,acc[3][1]);
            acc[4][0]=fma2(a45.x,b.x,acc[4][0]); acc[4][1]=fma2(a45.x,b.y,acc[4][1]);
            acc[5][0]=fma2(a45.y,b.x,acc[5][0]); acc[5][1]=fma2(a45.y,b.y,acc[5][1]);
            acc[6][0]=fma2(a67.x,b.x,acc[6][0]); acc[6][1]=fma2(a67.x,b.y,acc[6][1]);
            acc[7][0]=fma2(a67.y,b.x,acc[7][0]); acc[7][1]=fma2(a67.y,b.y,acc[7][1]);
        }
        if (c + 1 < NC) sg.AsD[(c+1)&1][ak][ar] = pack2(aNext, aNext);
        __syncthreads();
    }
    #undef STAGE_B

    // split-K reduce through smem (aliases Bs)
    float* Red = (float*)&sg.Bs[0][0][0];
    #pragma unroll
    for (int r = 0; r < 8; r++) {
        float x0, x1, x2, x3;
        unpack2(acc[r][0], x0, x1);
        unpack2(acc[r][1], x2, x3);
        *(float4*)&Red[((w << 3) + r)*CC + (lane << 2)] = make_float4(x0, x1, x2, x3);
    }
    __syncthreads();
    const int rr = tid >> 5, c4 = (tid & 31) << 2;
    float4 s = *(float4*)&Red[(rr)*CC + c4];
    #pragma unroll
    for (int j = 1; j < 8; j++) {
        float4 t = *(float4*)&Red[((j << 3) + rr)*CC + c4];
        s.x += t.x; s.y += t.y; s.z += t.z; s.w += t.w;
    }
    outv[0] = s.x; outv[1] = s.y; outv[2] = s.z; outv[3] = s.w;
    // no trailing sync: next gemm_v2's entry sync protects Red.
}

// ================= K1: LN1 + TemporalShift + r/k/v GEMMs (row-local fusion) ========
struct __align__(16) SmemK1 {
    SmemGemm gem;            // 36864
    float lnaux[10][CC];     //  5120
    float hss[8*132];        //  4224
};                           // 46208 < 48K static

__global__ void __launch_bounds__(256, 1)
k1_kernel(const float* __restrict__ x,
          const float* __restrict__ ln1_g, const float* __restrict__ ln1_b,
          const float* __restrict__ mu,
          const float* __restrict__ Wr, const float* __restrict__ br,
          const float* __restrict__ Wk, const float* __restrict__ bk,
          const float* __restrict__ Wv, const float* __restrict__ bv) {
    __shared__ SmemK1 S;
    const int tid = threadIdx.x, w = tid >> 5, lane = tid & 31;
    const int b  = blockIdx.x >> 6;
    const int t0 = (blockIdx.x & 63) << 3;
    const int bm = blockIdx.x << 3;

    // LN1 + shift (8 rows + halo) -> hss
    {
        float4 g4 = *(const float4*)(ln1_g + (lane << 2));
        float4 b4 = *(const float4*)(ln1_b + (lane << 2));
        for (int hr = w; hr < 10; hr += 8) {
            int t = t0 - 1 + hr;
            bool ok = (t >= 0) && (t < TT);
            float4 xv = make_float4(0.f, 0.f, 0.f, 0.f);
            if (ok) xv = *(const float4*)(x + (size_t)((b << 9) + t)*CC + (lane << 2));
            float mean = wsum((xv.x + xv.y) + (xv.z + xv.w)) * (1.0f/CC);
            float d0 = xv.x - mean, d1 = xv.y - mean, d2 = xv.z - mean, d3 = xv.w - mean;
            float rs = rsqrtf(wsum((d0*d0 + d1*d1) + (d2*d2 + d3*d3)) * (1.0f/CC) + 1e-5f);
            int c = lane << 2;
            S.lnaux[hr][c+0] = ok ? d0*rs*g4.x + b4.x : 0.f;
            S.lnaux[hr][c+1] = ok ? d1*rs*g4.y + b4.y : 0.f;
            S.lnaux[hr][c+2] = ok ? d2*rs*g4.z + b4.z : 0.f;
            S.lnaux[hr][c+3] = ok ? d3*rs*g4.w + b4.w : 0.f;
        }
        __syncthreads();
        for (int i = tid; i < 8*CC; i += 256) {
            int rl = i >> 7, c = i & (CC-1);
            float val = S.lnaux[rl+1][c];
            float shv = (c < CC/2) ? S.lnaux[rl][c] : S.lnaux[rl+2][c];
            S.hss[rl*132 + c] = val + mu[c]*shv;
        }
    }

    float ov[4];
    const int rr = tid >> 5, c4 = (tid & 31) << 2;
    // V
    gemm_v2<CC>(S.gem, S.hss, 132, 0, Wv, CC, 0, ov);
    {
        float4 b4 = *(const float4*)(bv + c4);
        *(float4*)(g_v + (size_t)(bm + rr)*CC + c4) =
            make_float4(ov[0]+b4.x, ov[1]+b4.y, ov[2]+b4.z, ov[3]+b4.w);
    }
    // K
    gemm_v2<CC>(S.gem, S.hss, 132, 0, Wk, CC, 0, ov);
    {
        float4 b4 = *(const float4*)(bk + c4);
        *(float4*)(g_k + (size_t)(bm + rr)*CC + c4) =
            make_float4(ov[0]+b4.x, ov[1]+b4.y, ov[2]+b4.z, ov[3]+b4.w);
    }
    // R (sigmoid)
    gemm_v2<CC>(S.gem, S.hss, 132, 0, Wr, CC, 0, ov);
    {
        float4 b4 = *(const float4*)(br + c4);
        float v0 = ov[0]+b4.x, v1 = ov[1]+b4.y, v2 = ov[2]+b4.z, v3 = ov[3]+b4.w;
        *(float4*)(g_r + (size_t)(bm + rr)*CC + c4) =
            make_float4(1.0f/(1.0f+expf(-v0)), 1.0f/(1.0f+expf(-v1)),
                        1.0f/(1.0f+expf(-v2)), 1.0f/(1.0f+expf(-v3)));
    }
}

// ---------------- WKV v3 (round-16 proven): 2 rows/warp ----------------
__global__ void __launch_bounds__(512, 1)
wkv_kernel(const float* __restrict__ k, const float* __restrict__ v,
           const float* __restrict__ r, const float* __restrict__ wd,
           float* __restrict__ wk) {
    __shared__ float s_acc[4][8][CC];
    const int tid = threadIdx.x;
    const int wid = tid >> 5, lane = tid & 31;
    const int seg = wid & 3, rp = wid >> 2;
    const int row0 = (blockIdx.x << 3) + (rp << 1);
    const int bb  = row0 >> 9;
    const int h = lane >> 4, p = lane & 15;
    const int c0 = p << 3;

    const float inv511 = 1.0f/511.0f;
    const int l0 = seg << 7;
    const float s0 = (float)(511 - (l0 + h)) * inv511;

    float nw[8];
    {
        float4 w0 = *(const float4*)(wd + c0);
        float4 w1 = *(const float4*)(wd + c0 + 4);
        nw[0] = -expf(w0.x); nw[1] = -expf(w0.y); nw[2] = -expf(w0.z); nw[3] = -expf(w0.w);
        nw[4] = -expf(w1.x); nw[5] = -expf(w1.y); nw[6] = -expf(w1.z); nw[7] = -expf(w1.w);
    }

    ull E[2][4], G[2][4], acc[2][4];
    #pragma unroll
    for (int rr = 0; rr < 2; rr++) {
        float bv8[8];
        float4 k0 = *(const float4*)(k + (size_t)(row0 + rr)*CC + c0);
        float4 k1 = *(const float4*)(k + (size_t)(row0 + rr)*CC + c0 + 4);
        bv8[0] = k0.x*nw[0]; bv8[1] = k0.y*nw[1]; bv8[2] = k0.z*nw[2]; bv8[3] = k0.w*nw[3];
        bv8[4] = k1.x*nw[4]; bv8[5] = k1.y*nw[5]; bv8[6] = k1.z*nw[6]; bv8[7] = k1.w*nw[7];
        float amax = bv8[0];
        #pragma unroll
        for (int i = 1; i < 8; i++) amax = fmaxf(amax, bv8[i]);
        #pragma unroll
        for (int o = 16; o; o >>= 1) amax = fmaxf(amax, __shfl_xor_sync(0xffffffffu, amax, o));
        #pragma unroll
        for (int i = 0; i < 8; i++) bv8[i] -= amax;
        #pragma unroll
        for (int j = 0; j < 4; j++) {
            E[rr][j]   = pack2(expf(bv8[2*j]*s0),           expf(bv8[2*j+1]*s0));
            G[rr][j]   = pack2(expf(-2.0f*bv8[2*j]*inv511), expf(-2.0f*bv8[2*j+1]*inv511));
            acc[rr][j] = 0ull;
        }
    }

    const float* vp = v + ((size_t)(bb << 9) + l0 + h)*CC + c0;

    #pragma unroll 2
    for (int i = 0; i < 64; i++) {
        ulonglong2 v01 = *(const ulonglong2*)(vp);
        ulonglong2 v23 = *(const ulonglong2*)(vp + 4);
        #pragma unroll
        for (int rr = 0; rr < 2; rr++) {
            ull t = add2(add2(E[rr][0], E[rr][1]), add2(E[rr][2], E[rr][3]));
            float zl, zh; unpack2(t, zl, zh);
            float z = zl + zh;
            #pragma unroll
            for (int o = 8; o; o >>= 1) z += __shfl_xor_sync(0xffffffffu, z, o);
            float inv = rcpa(z + 1e-6f);
            ull invd = pack2(inv, inv);
            acc[rr][0] = fma2(mul2(E[rr][0], invd), v01.x, acc[rr][0]);
            acc[rr][1] = fma2(mul2(E[rr][1], invd), v01.y, acc[rr][1]);
            acc[rr][2] = fma2(mul2(E[rr][2], invd), v23.x, acc[rr][2]);
            acc[rr][3] = fma2(mul2(E[rr][3], invd), v23.y, acc[rr][3]);
            E[rr][0] = mul2(E[rr][0], G[rr][0]); E[rr][1] = mul2(E[rr][1], G[rr][1]);
            E[rr][2] = mul2(E[rr][2], G[rr][2]); E[rr][3] = mul2(E[rr][3], G[rr][3]);
        }
        vp += 2*CC;
    }

    #pragma unroll
    for (int rr = 0; rr < 2; rr++) {
        #pragma unroll
        for (int j = 0; j < 4; j++) {
            float x, y; unpack2(acc[rr][j], x, y);
            x += __shfl_xor_sync(0xffffffffu, x, 16);
            y += __shfl_xor_sync(0xffffffffu, y, 16);
            if (h == 0) {
                s_acc[seg][(rp << 1) + rr][c0 + 2*j    ] = x;
                s_acc[seg][(rp << 1) + rr][c0 + 2*j + 1] = y;
            }
        }
    }
    __syncthreads();

    for (int idx = tid; idx < 8*CC; idx += 512) {
        const int rl = idx >> 7, c = idx & (CC-1);
        float sum = (s_acc[0][rl][c] + s_acc[1][rl][c]) + (s_acc[2][rl][c] + s_acc[3][rl][c]);
        const int grow = (blockIdx.x << 3) + rl;
        wk[(size_t)grow*CC + c] = r[(size_t)grow*CC + c] * sum;
    }
}

// ================= K3: Wo + LN2 + W1(gelu) + W2 (row-local fusion) =================
struct __align__(16) SmemK3 {
    SmemGemm gem;            // 36864
    float mid[8*516];        // 16512 (pad 516 -> conflict-free A reads)
    float h2s[8*132];        //  4224
    float ys [8*CC];         //  4096
};                           // 61696 -> dynamic smem

__global__ void __launch_bounds__(256, 1)
k3_kernel(const float* __restrict__ wkin,
          const float* __restrict__ Wo, const float* __restrict__ bo,
          const float* __restrict__ x,
          const float* __restrict__ g2, const float* __restrict__ be2,
          const float* __restrict__ W1, const float* __restrict__ b1,
          const float* __restrict__ W2, const float* __restrict__ b2,
          float* __restrict__ out) {
    extern __shared__ __align__(16) char smem_raw[];
    SmemK3* S = (SmemK3*)smem_raw;
    const int tid = threadIdx.x;
    const int bm = blockIdx.x << 3;
    const int rr = tid >> 5, c4 = (tid & 31) << 2;
    const int m = bm + rr;

    float ov[4];
    // ---- Wo + bias + residual -> ys; LN2 -> h2s ----
    gemm_v2<CC>(S->gem, wkin, CC, bm, Wo, CC, 0, ov);
    {
        float4 b4v = *(const float4*)(bo  + c4);
        float4 g4  = *(const float4*)(g2  + c4);
        float4 b4  = *(const float4*)(be2 + c4);
        float4 xv  = *(const float4*)(x + (size_t)m*CC + c4);
        float y0 = ov[0] + b4v.x + xv.x;
        float y1 = ov[1] + b4v.y + xv.y;
        float y2 = ov[2] + b4v.z + xv.z;
        float y3 = ov[3] + b4v.w + xv.w;
        *(float4*)&S->ys[rr*CC + c4] = make_float4(y0, y1, y2, y3);
        float mean = wsum((y0 + y1) + (y2 + y3)) * (1.0f/CC);
        float d0 = y0 - mean, d1 = y1 - mean, d2 = y2 - mean, d3 = y3 - mean;
        float rs = rsqrtf(wsum((d0*d0 + d1*d1) + (d2*d2 + d3*d3)) * (1.0f/CC) + 1e-5f);
        S->h2s[rr*132 + c4 + 0] = d0*rs*g4.x + b4.x;
        S->h2s[rr*132 + c4 + 1] = d1*rs*g4.y + b4.y;
        S->h2s[rr*132 + c4 + 2] = d2*rs*g4.z + b4.z;
        S->h2s[rr*132 + c4 + 3] = d3*rs*g4.w + b4.w;
    }

    // ---- W1 + exact gelu (4 n-tiles) -> mid ----
    #pragma unroll 1
    for (int nb = 0; nb < 4; nb++) {
        gemm_v2<CC>(S->gem, S->h2s, 132, 0, W1, HH, nb << 7, ov);
        float4 b4v = *(const float4*)(b1 + (nb << 7) + c4);
        float v0 = ov[0]+b4v.x, v1 = ov[1]+b4v.y, v2 = ov[2]+b4v.z, v3 = ov[3]+b4v.w;
        const float gc = 0.70710678118654752f;
        v0 = 0.5f*v0*(1.0f + erff(v0*gc));
        v1 = 0.5f*v1*(1.0f + erff(v1*gc));
        v2 = 0.5f*v2*(1.0f + erff(v2*gc));
        v3 = 0.5f*v3*(1.0f + erff(v3*gc));
        *(float4*)&S->mid[rr*516 + (nb << 7) + c4] = make_float4(v0, v1, v2, v3);
    }

    // ---- W2 (K=512) + bias + residual -> out ----
    gemm_v2<HH>(S->gem, S->mid, 516, 0, W2, CC, 0, ov);
    {
        float4 b4v = *(const float4*)(b2 + c4);
        float4 yv  = *(float4*)&S->ys[rr*CC + c4];
        *(float4*)(out + (size_t)m*CC + c4) =
            make_float4(ov[0] + b4v.x + yv.x, ov[1] + b4v.y + yv.y,
                        ov[2] + b4v.z + yv.z, ov[3] + b4v.w + yv.w);
    }
}

// ---------------- launch ----------------
extern "C" void kernel_launch(void* const* d_in, const int* in_sizes, int n_in,
                              void* d_out, int out_size) {
    const float* x       = (const float*)d_in[0];
    const float* ln1_g   = (const float*)d_in[1];
    const float* ln1_b   = (const float*)d_in[2];
    const float* mu      = (const float*)d_in[3];
    const float* Wr      = (const float*)d_in[4];
    const float* br      = (const float*)d_in[5];
    const float* Wk      = (const float*)d_in[6];
    const float* bk      = (const float*)d_in[7];
    const float* Wv      = (const float*)d_in[8];
    const float* bv      = (const float*)d_in[9];
    const float* w_decay = (const float*)d_in[10];
    const float* Wo      = (const float*)d_in[11];
    const float* bo      = (const float*)d_in[12];
    const float* ln2_g   = (const float*)d_in[13];
    const float* ln2_b   = (const float*)d_in[14];
    const float* W1      = (const float*)d_in[15];
    const float* b1      = (const float*)d_in[16];
    const float* W2      = (const float*)d_in[17];
    const float* b2      = (const float*)d_in[18];
    float* out = (float*)d_out;

    float *r_, *k_, *v_, *wkp;
    cudaGetSymbolAddress((void**)&r_,  g_r);
    cudaGetSymbolAddress((void**)&k_,  g_k);
    cudaGetSymbolAddress((void**)&v_,  g_v);
    cudaGetSymbolAddress((void**)&wkp, g_wk);

    // opt-in every call (no static guards); attribute set is idempotent
    cudaFuncSetAttribute(k3_kernel, cudaFuncAttributeMaxDynamicSharedMemorySize,
                         (int)sizeof(SmemK3));

    k1_kernel<<<128, 256>>>(x, ln1_g, ln1_b, mu, Wr, br, Wk, bk, Wv, bv);
    wkv_kernel<<<128, 512>>>(k_, v_, r_, w_decay, wkp);
    k3_kernel<<<128, 256, sizeof(SmemK3)>>>(wkp, Wo, bo, x, ln2_g, ln2_b,
                                            W1, b1, W2, b2, out);
}